// round 14
// baseline (speedup 1.0000x reference)
#include <cuda_runtime.h>
#include <cuda_bf16.h>
#include <mma.h>
#include <cstdint>

using namespace nvcuda;

// Problem constants (match reference setup_inputs)
#define N_NODES 100000
#define N_EDGES 600000
#define IN_DIM  128
#define OUT_DIM 64
#define PAD_ROWS 128
#define SCAN_BLOCKS ((N_NODES + 255) / 256)   // 391

// -------- device-global scratch (no allocations allowed) --------
__device__ float4 g_aggx_v[(size_t)(N_NODES + PAD_ROWS) * IN_DIM / 4];  // A @ x (tf32)
__device__ float4 g_t2_v[(size_t)(N_NODES + PAD_ROWS) * OUT_DIM / 4];   // fused gemm out
__device__ int    g_src[N_EDGES];
__device__ int    g_dst[N_EDGES];
__device__ int    g_ord[N_EDGES];      // per-dst ordinal from decode's atomic
__device__ int    g_cnt[N_NODES];      // per-dst degree (memset to 0 each call)
__device__ int    g_ptrl[N_NODES + 1]; // block-LOCAL exclusive prefix of degrees
__device__ int    g_blkx[SCAN_BLOCKS]; // exclusive prefix of block sums
__device__ int    g_blk[SCAN_BLOCKS];  // block sums
__device__ int4   g_csr_v[N_EDGES / 2 + 1];  // 16B-aligned; viewed as int2 records
// final ptr of node m = g_ptrl[m] + g_blkx[m >> 8]

// -------- edge-index decode (int32/int64 autodetect) + degree/ordinal --------
__device__ __forceinline__ bool ei_is_int64(const void* p) {
    const long long* q = (const long long*)p;
    #pragma unroll
    for (int i = 0; i < 4; i++) {
        long long v = q[i];
        if (v < 0 || v >= N_NODES) return false;
    }
    return true;
}

__global__ __launch_bounds__(256) void decode_edges(const void* __restrict__ ei, int E) {
    int e = blockIdx.x * blockDim.x + threadIdx.x;
    if (e >= E) return;
    long long s, d;
    if (ei_is_int64(ei)) {
        const long long* q = (const long long*)ei;
        s = q[e]; d = q[(size_t)E + e];
    } else {
        const int* q = (const int*)ei;
        s = q[e]; d = q[(size_t)E + e];
    }
    if (s < 0 || s >= N_NODES) s = 0;
    if (d < 0 || d >= N_NODES) d = 0;
    g_src[e] = (int)s;
    g_dst[e] = (int)d;
    g_ord[e] = atomicAdd(&g_cnt[(int)d], 1);   // degree count + unique ordinal
}

// -------- scan1: per-256-block shfl scan of degrees --------
__global__ __launch_bounds__(256) void scan1() {
    __shared__ int wsum[8];
    const int tid = threadIdx.x;
    const int i = blockIdx.x * 256 + tid;
    const int lane = tid & 31;
    const int w = tid >> 5;

    int v = (i < N_NODES) ? g_cnt[i] : 0;
    int x = v;
    #pragma unroll
    for (int o = 1; o < 32; o <<= 1) {
        int t = __shfl_up_sync(0xFFFFFFFFu, x, o);
        if (lane >= o) x += t;
    }
    if (lane == 31) wsum[w] = x;
    __syncthreads();
    if (w == 0) {
        int y = (lane < 8) ? wsum[lane] : 0;
        #pragma unroll
        for (int o = 1; o < 8; o <<= 1) {
            int t = __shfl_up_sync(0xFFFFFFFFu, y, o);
            if (lane >= o) y += t;
        }
        if (lane < 8) wsum[lane] = y;
    }
    __syncthreads();
    const int incl = x + (w > 0 ? wsum[w - 1] : 0);
    if (i < N_NODES) g_ptrl[i] = incl - v;          // block-local exclusive
    if (i == N_NODES - 1) g_ptrl[N_NODES] = incl;   // boundary (same block: 390)
    if (tid == 255) g_blk[blockIdx.x] = wsum[7];    // block total
}

// -------- scan2: one block, exclusive shfl scan of the 391 block sums --------
__global__ __launch_bounds__(512) void scan2() {
    __shared__ int wsum[16];
    const int tid = threadIdx.x;
    const int lane = tid & 31;
    const int w = tid >> 5;
    int v = (tid < SCAN_BLOCKS) ? g_blk[tid] : 0;
    int x = v;
    #pragma unroll
    for (int o = 1; o < 32; o <<= 1) {
        int t = __shfl_up_sync(0xFFFFFFFFu, x, o);
        if (lane >= o) x += t;
    }
    if (lane == 31) wsum[w] = x;
    __syncthreads();
    if (w == 0) {
        int y = (lane < 16) ? wsum[lane] : 0;
        #pragma unroll
        for (int o = 1; o < 16; o <<= 1) {
            int t = __shfl_up_sync(0xFFFFFFFFu, y, o);
            if (lane >= o) y += t;
        }
        if (lane < 16) wsum[lane] = y;
    }
    __syncthreads();
    const int excl = x - v + (w > 0 ? wsum[w - 1] : 0);
    if (tid < SCAN_BLOCKS) g_blkx[tid] = excl;
}

// -------- fill CSR: no atomics (ordinal precomputed in decode) --------
__global__ __launch_bounds__(256) void fill_csr(const float* __restrict__ ew, int E) {
    int e = blockIdx.x * blockDim.x + threadIdx.x;
    if (e >= E) return;
    const int d = g_dst[e];
    const int pos = g_ptrl[d] + g_blkx[d >> 8] + g_ord[e];
    ((int2*)g_csr_v)[pos] = make_int2(g_src[e], __float_as_int(ew[e]));
}

// -------- gather SpMM layer 1: aggx[n] = tf32(sum w_e * x[src_e])  (warp/node) --------
// Paired int4 edge loads (2 records) + 4-wide feature-gather MLP.
__global__ __launch_bounds__(256) void gather1(const float* __restrict__ x,
                                               float* __restrict__ aggx) {
    const int n = (blockIdx.x * 256 + threadIdx.x) >> 5;
    const int lane = threadIdx.x & 31;
    if (n >= N_NODES) return;
    const int beg = g_ptrl[n] + g_blkx[n >> 8];
    const int end = g_ptrl[n + 1] + g_blkx[(n + 1) >> 8];
    const int2* csr = (const int2*)g_csr_v;
    float4 acc = make_float4(0.f, 0.f, 0.f, 0.f);
    int e = beg;
    if ((e & 1) && e < end) {           // align to int4 boundary
        const int2 p = __ldg(&csr[e]);
        const float w = __int_as_float(p.y);
        const float4 v = __ldg(((const float4*)(x + (size_t)p.x * IN_DIM)) + lane);
        acc.x += w * v.x; acc.y += w * v.y; acc.z += w * v.z; acc.w += w * v.w;
        e++;
    }
    for (; e + 4 <= end; e += 4) {      // 2 int4 loads = 4 edges
        const int4 q0 = __ldg((const int4*)&csr[e]);
        const int4 q1 = __ldg((const int4*)&csr[e + 2]);
        const float4 v0 = __ldg(((const float4*)(x + (size_t)q0.x * IN_DIM)) + lane);
        const float4 v1 = __ldg(((const float4*)(x + (size_t)q0.z * IN_DIM)) + lane);
        const float4 v2 = __ldg(((const float4*)(x + (size_t)q1.x * IN_DIM)) + lane);
        const float4 v3 = __ldg(((const float4*)(x + (size_t)q1.z * IN_DIM)) + lane);
        const float w0 = __int_as_float(q0.y), w1 = __int_as_float(q0.w);
        const float w2 = __int_as_float(q1.y), w3 = __int_as_float(q1.w);
        acc.x += w0 * v0.x + w1 * v1.x + w2 * v2.x + w3 * v3.x;
        acc.y += w0 * v0.y + w1 * v1.y + w2 * v2.y + w3 * v3.y;
        acc.z += w0 * v0.z + w1 * v1.z + w2 * v2.z + w3 * v3.z;
        acc.w += w0 * v0.w + w1 * v1.w + w2 * v2.w + w3 * v3.w;
    }
    for (; e < end; e++) {
        const int2 p = __ldg(&csr[e]);
        const float w = __int_as_float(p.y);
        const float4 v = __ldg(((const float4*)(x + (size_t)p.x * IN_DIM)) + lane);
        acc.x += w * v.x; acc.y += w * v.y; acc.z += w * v.z; acc.w += w * v.w;
    }
    // pre-round to tf32 so the fused gemm needs no per-fragment fixup
    acc.x = wmma::__float_to_tf32(acc.x);
    acc.y = wmma::__float_to_tf32(acc.y);
    acc.z = wmma::__float_to_tf32(acc.z);
    acc.w = wmma::__float_to_tf32(acc.w);
    ((float4*)(aggx + (size_t)n * IN_DIM))[lane] = acc;
}

// -------- gather SpMM layer 2: out[n] = b2 + sum w_e * t2[src]  (halfwarp/node) --------
__global__ __launch_bounds__(256) void gather2(const float* __restrict__ t2,
                                               const float* __restrict__ b2,
                                               float* __restrict__ out) {
    const int n = (blockIdx.x * 256 + threadIdx.x) >> 4;
    const int lane = threadIdx.x & 15;
    if (n >= N_NODES) return;
    const int beg = g_ptrl[n] + g_blkx[n >> 8];
    const int end = g_ptrl[n + 1] + g_blkx[(n + 1) >> 8];
    const int2* csr = (const int2*)g_csr_v;
    float4 acc = __ldg(((const float4*)b2) + lane);
    int e = beg;
    if ((e & 1) && e < end) {
        const int2 p = __ldg(&csr[e]);
        const float w = __int_as_float(p.y);
        const float4 v = __ldg(((const float4*)(t2 + (size_t)p.x * OUT_DIM)) + lane);
        acc.x += w * v.x; acc.y += w * v.y; acc.z += w * v.z; acc.w += w * v.w;
        e++;
    }
    for (; e + 4 <= end; e += 4) {
        const int4 q0 = __ldg((const int4*)&csr[e]);
        const int4 q1 = __ldg((const int4*)&csr[e + 2]);
        const float4 v0 = __ldg(((const float4*)(t2 + (size_t)q0.x * OUT_DIM)) + lane);
        const float4 v1 = __ldg(((const float4*)(t2 + (size_t)q0.z * OUT_DIM)) + lane);
        const float4 v2 = __ldg(((const float4*)(t2 + (size_t)q1.x * OUT_DIM)) + lane);
        const float4 v3 = __ldg(((const float4*)(t2 + (size_t)q1.z * OUT_DIM)) + lane);
        const float w0 = __int_as_float(q0.y), w1 = __int_as_float(q0.w);
        const float w2 = __int_as_float(q1.y), w3 = __int_as_float(q1.w);
        acc.x += w0 * v0.x + w1 * v1.x + w2 * v2.x + w3 * v3.x;
        acc.y += w0 * v0.y + w1 * v1.y + w2 * v2.y + w3 * v3.y;
        acc.z += w0 * v0.z + w1 * v1.z + w2 * v2.z + w3 * v3.z;
        acc.w += w0 * v0.w + w1 * v1.w + w2 * v2.w + w3 * v3.w;
    }
    for (; e < end; e++) {
        const int2 p = __ldg(&csr[e]);
        const float w = __int_as_float(p.y);
        const float4 v = __ldg(((const float4*)(t2 + (size_t)p.x * OUT_DIM)) + lane);
        acc.x += w * v.x; acc.y += w * v.y; acc.z += w * v.z; acc.w += w * v.w;
    }
    ((float4*)(out + (size_t)n * OUT_DIM))[lane] = acc;
}

// -------- fused GEMM: t2 = relu(aggx @ W1 + b1) @ W2  (tf32 tensor cores) --------
// 256 thr / 8 warps / 128 rows. smem = 102.5 KB -> 2 blocks/SM (regs capped 128).
// Stage-1 A-fragments are double-buffered: the next global load is issued
// before the 8 MMAs consume the current one, hiding L2 latency.
#define LDW1 132
#define LDW2 72

__global__ __launch_bounds__(256, 2) void fused_gemm(const float* __restrict__ A,
                                                     const float* __restrict__ W1g,
                                                     const float* __restrict__ b1g,
                                                     const float* __restrict__ W2g,
                                                     float* __restrict__ t2) {
    extern __shared__ float smem[];
    float* sW1 = smem;                          // 128 x LDW1 (later: staging)
    float* sW2 = sW1 + 128 * LDW1;              // 128 x LDW2
    float* sB1 = sW2 + 128 * LDW2;              // 128

    const int t = threadIdx.x;
    for (int i = t; i < 128 * 128; i += 256)
        sW1[(i >> 7) * LDW1 + (i & 127)] = wmma::__float_to_tf32(W1g[i]);
    for (int i = t; i < 128 * 64; i += 256)
        sW2[(i >> 6) * LDW2 + (i & 63)] = wmma::__float_to_tf32(W2g[i]);
    if (t < 128) sB1[t] = b1g[t];
    __syncthreads();

    const int warp = t >> 5;
    const int lane = t & 31;
    const size_t row0 = (size_t)blockIdx.x * 128 + warp * 16;
    float* stg = sW1 + warp * 16 * LDW1;        // this warp's staging strip
    const float* Arow = A + row0 * 128;

    wmma::fragment<wmma::matrix_a, 16, 16, 8, wmma::precision::tf32, wmma::row_major> af[2];
    wmma::fragment<wmma::matrix_b, 16, 16, 8, wmma::precision::tf32, wmma::row_major> bf;

    // ---- stage 1: acc = A_strip @ W1 (double-buffered af) ----
    {
        wmma::fragment<wmma::accumulator, 16, 16, 8, float> acc[8];
        #pragma unroll
        for (int n = 0; n < 8; n++) wmma::fill_fragment(acc[n], 0.f);

        wmma::load_matrix_sync(af[0], Arow, 128);
        #pragma unroll
        for (int k = 0; k < 16; k++) {
            if (k < 15)
                wmma::load_matrix_sync(af[(k + 1) & 1], Arow + (k + 1) * 8, 128);
            #pragma unroll
            for (int n = 0; n < 8; n++) {
                wmma::load_matrix_sync(bf, sW1 + (k * 8) * LDW1 + n * 16, LDW1);
                wmma::mma_sync(acc[n], af[k & 1], bf, acc[n]);
            }
        }
        __syncthreads();   // all warps done reading W1 -> safe to overwrite
        #pragma unroll
        for (int n = 0; n < 8; n++)
            wmma::store_matrix_sync(stg + n * 16, acc[n], LDW1, wmma::mem_row_major);
    }
    __syncwarp();

    // ---- bias + relu + tf32-round on this warp's strip (in smem) ----
    for (int i = lane; i < 16 * 32; i += 32) {   // 16 rows x 32 float4
        const int r = i >> 5;
        const int c4 = (i & 31) * 4;
        float* p = stg + r * LDW1 + c4;
        p[0] = wmma::__float_to_tf32(fmaxf(p[0] + sB1[c4 + 0], 0.f));
        p[1] = wmma::__float_to_tf32(fmaxf(p[1] + sB1[c4 + 1], 0.f));
        p[2] = wmma::__float_to_tf32(fmaxf(p[2] + sB1[c4 + 2], 0.f));
        p[3] = wmma::__float_to_tf32(fmaxf(p[3] + sB1[c4 + 3], 0.f));
    }
    __syncwarp();

    // ---- stage 2: t2_strip = strip @ W2 ----
    {
        wmma::fragment<wmma::accumulator, 16, 16, 8, float> acc2[4];
        #pragma unroll
        for (int n = 0; n < 4; n++) wmma::fill_fragment(acc2[n], 0.f);

        #pragma unroll
        for (int k = 0; k < 16; k++) {
            wmma::load_matrix_sync(af[0], stg + k * 8, LDW1);
            #pragma unroll
            for (int n = 0; n < 4; n++) {
                wmma::load_matrix_sync(bf, sW2 + (k * 8) * LDW2 + n * 16, LDW2);
                wmma::mma_sync(acc2[n], af[0], bf, acc2[n]);
            }
        }
        #pragma unroll
        for (int n = 0; n < 4; n++)
            wmma::store_matrix_sync(t2 + row0 * 64 + n * 16, acc2[n],
                                    64, wmma::mem_row_major);
    }
}

extern "C" void kernel_launch(void* const* d_in, const int* in_sizes, int n_in,
                              void* d_out, int out_size) {
    // Identify inputs by element count (robust to metadata ordering)
    const float* x  = nullptr; const void* ei = nullptr; const float* ew = nullptr;
    const float* W1 = nullptr; const float* b1 = nullptr;
    const float* W2 = nullptr; const float* b2 = nullptr;
    for (int i = 0; i < n_in; i++) {
        switch (in_sizes[i]) {
            case 12800000: x  = (const float*)d_in[i]; break;
            case 1200000:  ei = d_in[i];               break;
            case 600000:   ew = (const float*)d_in[i]; break;
            case 16384:    W1 = (const float*)d_in[i]; break;
            case 128:      b1 = (const float*)d_in[i]; break;
            case 8192:     W2 = (const float*)d_in[i]; break;
            case 64:       b2 = (const float*)d_in[i]; break;
            default: break;
        }
    }
    float* out = (float*)d_out;
    const int E = N_EDGES;

    float* aggx; cudaGetSymbolAddress((void**)&aggx, g_aggx_v);
    float* t2;   cudaGetSymbolAddress((void**)&t2,   g_t2_v);
    void*  cp;   cudaGetSymbolAddress(&cp, g_cnt);

    const int smemF = (128 * LDW1 + 128 * LDW2 + 128) * 4;   // 102.5 KB
    cudaFuncSetAttribute(fused_gemm, cudaFuncAttributeMaxDynamicSharedMemorySize,
                         smemF);

    // --- CSR build: memset + decode + scan1 + scan2 + fill ---
    cudaMemsetAsync(cp, 0, N_NODES * sizeof(int));
    decode_edges<<<(E + 255) / 256, 256>>>(ei, E);
    scan1<<<SCAN_BLOCKS, 256>>>();
    scan2<<<1, 512>>>();
    fill_csr<<<(E + 255) / 256, 256>>>(ew, E);

    // --- layer 1: aggx = tf32(A @ x)  (pull-mode gather, warp per node) ---
    gather1<<<(N_NODES * 32 + 255) / 256, 256>>>(x, aggx);

    // --- t2 = relu(aggx @ W1 + b1) @ W2  (single fused launch) ---
    const int gblocks = (N_NODES + 127) / 128;  // 782 (padding covers tail rows)
    fused_gemm<<<gblocks, 256, smemF>>>(aggx, W1, b1, W2, t2);

    // --- layer 2: out = b2 + A @ t2  (half-warp per node) ---
    gather2<<<(N_NODES * 16 + 255) / 256, 256>>>(t2, b2, out);
}

// round 16
// speedup vs baseline: 1.4541x; 1.4541x over previous
#include <cuda_runtime.h>
#include <cuda_bf16.h>
#include <mma.h>
#include <cstdint>

using namespace nvcuda;

// Problem constants (match reference setup_inputs)
#define N_NODES 100000
#define N_EDGES 600000
#define IN_DIM  128
#define OUT_DIM 64
#define PAD_ROWS 128
#define SCAN_BLOCKS ((N_NODES + 255) / 256)   // 391

// -------- device-global scratch (no allocations allowed) --------
__device__ float4 g_aggx_v[(size_t)(N_NODES + PAD_ROWS) * IN_DIM / 4];  // A @ x (tf32)
__device__ float4 g_t2_v[(size_t)(N_NODES + PAD_ROWS) * OUT_DIM / 4];   // fused gemm out
__device__ int    g_src[N_EDGES];
__device__ int    g_dst[N_EDGES];
__device__ int    g_ord[N_EDGES];      // per-dst ordinal from decode's atomic
__device__ int    g_cnt[N_NODES];      // zero-init; re-zeroed by fill_csr each call
__device__ int    g_ptrl[N_NODES + 1]; // block-LOCAL exclusive prefix of degrees
__device__ int    g_blkx[SCAN_BLOCKS]; // exclusive prefix of block sums
__device__ int    g_blk[SCAN_BLOCKS];  // block sums
__device__ int2   g_csr[N_EDGES];      // packed {src, float_bits(w)}
// final ptr of node m = g_ptrl[m] + g_blkx[m >> 8]

// -------- edge-index decode (int32/int64 autodetect) + degree/ordinal --------
__device__ __forceinline__ bool ei_is_int64(const void* p) {
    const long long* q = (const long long*)p;
    #pragma unroll
    for (int i = 0; i < 4; i++) {
        long long v = q[i];
        if (v < 0 || v >= N_NODES) return false;
    }
    return true;
}

__global__ __launch_bounds__(256) void decode_edges(const void* __restrict__ ei, int E) {
    int e = blockIdx.x * blockDim.x + threadIdx.x;
    if (e >= E) return;
    long long s, d;
    if (ei_is_int64(ei)) {
        const long long* q = (const long long*)ei;
        s = q[e]; d = q[(size_t)E + e];
    } else {
        const int* q = (const int*)ei;
        s = q[e]; d = q[(size_t)E + e];
    }
    if (s < 0 || s >= N_NODES) s = 0;
    if (d < 0 || d >= N_NODES) d = 0;
    g_src[e] = (int)s;
    g_dst[e] = (int)d;
    g_ord[e] = atomicAdd(&g_cnt[(int)d], 1);   // degree count + unique ordinal
}

// -------- scan1: per-256-block shfl scan of degrees --------
__global__ __launch_bounds__(256) void scan1() {
    __shared__ int wsum[8];
    const int tid = threadIdx.x;
    const int i = blockIdx.x * 256 + tid;
    const int lane = tid & 31;
    const int w = tid >> 5;

    int v = (i < N_NODES) ? g_cnt[i] : 0;
    int x = v;
    #pragma unroll
    for (int o = 1; o < 32; o <<= 1) {
        int t = __shfl_up_sync(0xFFFFFFFFu, x, o);
        if (lane >= o) x += t;
    }
    if (lane == 31) wsum[w] = x;
    __syncthreads();
    if (w == 0) {
        int y = (lane < 8) ? wsum[lane] : 0;
        #pragma unroll
        for (int o = 1; o < 8; o <<= 1) {
            int t = __shfl_up_sync(0xFFFFFFFFu, y, o);
            if (lane >= o) y += t;
        }
        if (lane < 8) wsum[lane] = y;
    }
    __syncthreads();
    const int incl = x + (w > 0 ? wsum[w - 1] : 0);
    if (i < N_NODES) g_ptrl[i] = incl - v;          // block-local exclusive
    if (i == N_NODES - 1) g_ptrl[N_NODES] = incl;   // boundary (same block: 390)
    if (tid == 255) g_blk[blockIdx.x] = wsum[7];    // block total
}

// -------- scan2: one block, exclusive shfl scan of the 391 block sums --------
__global__ __launch_bounds__(512) void scan2() {
    __shared__ int wsum[16];
    const int tid = threadIdx.x;
    const int lane = tid & 31;
    const int w = tid >> 5;
    int v = (tid < SCAN_BLOCKS) ? g_blk[tid] : 0;
    int x = v;
    #pragma unroll
    for (int o = 1; o < 32; o <<= 1) {
        int t = __shfl_up_sync(0xFFFFFFFFu, x, o);
        if (lane >= o) x += t;
    }
    if (lane == 31) wsum[w] = x;
    __syncthreads();
    if (w == 0) {
        int y = (lane < 16) ? wsum[lane] : 0;
        #pragma unroll
        for (int o = 1; o < 16; o <<= 1) {
            int t = __shfl_up_sync(0xFFFFFFFFu, y, o);
            if (lane >= o) y += t;
        }
        if (lane < 16) wsum[lane] = y;
    }
    __syncthreads();
    const int excl = x - v + (w > 0 ? wsum[w - 1] : 0);
    if (tid < SCAN_BLOCKS) g_blkx[tid] = excl;
}

// -------- fill CSR: no atomics; also re-zeroes g_cnt for the next replay --------
// (scan1/scan2 are the last readers of g_cnt; zeroing here removes the
//  per-call cudaMemsetAsync launch. First replay sees the static zero-init.)
__global__ __launch_bounds__(256) void fill_csr(const float* __restrict__ ew, int E) {
    int e = blockIdx.x * blockDim.x + threadIdx.x;
    if (e < N_NODES) g_cnt[e] = 0;
    if (e >= E) return;
    const int d = g_dst[e];
    const int pos = g_ptrl[d] + g_blkx[d >> 8] + g_ord[e];
    g_csr[pos] = make_int2(g_src[e], __float_as_int(ew[e]));
}

// -------- gather SpMM layer 1: aggx[n] = tf32(sum w_e * x[src_e])  (warp/node) --------
__global__ __launch_bounds__(256) void gather1(const float* __restrict__ x,
                                               float* __restrict__ aggx) {
    const int n = (blockIdx.x * 256 + threadIdx.x) >> 5;
    const int lane = threadIdx.x & 31;
    if (n >= N_NODES) return;
    const int beg = g_ptrl[n] + g_blkx[n >> 8];
    const int end = g_ptrl[n + 1] + g_blkx[(n + 1) >> 8];
    float4 acc = make_float4(0.f, 0.f, 0.f, 0.f);
    int e = beg;
    for (; e + 4 <= end; e += 4) {
        const int2 p0 = __ldg(&g_csr[e + 0]);
        const int2 p1 = __ldg(&g_csr[e + 1]);
        const int2 p2 = __ldg(&g_csr[e + 2]);
        const int2 p3 = __ldg(&g_csr[e + 3]);
        const float4 v0 = __ldg(((const float4*)(x + (size_t)p0.x * IN_DIM)) + lane);
        const float4 v1 = __ldg(((const float4*)(x + (size_t)p1.x * IN_DIM)) + lane);
        const float4 v2 = __ldg(((const float4*)(x + (size_t)p2.x * IN_DIM)) + lane);
        const float4 v3 = __ldg(((const float4*)(x + (size_t)p3.x * IN_DIM)) + lane);
        const float w0 = __int_as_float(p0.y), w1 = __int_as_float(p1.y);
        const float w2 = __int_as_float(p2.y), w3 = __int_as_float(p3.y);
        acc.x += w0 * v0.x + w1 * v1.x + w2 * v2.x + w3 * v3.x;
        acc.y += w0 * v0.y + w1 * v1.y + w2 * v2.y + w3 * v3.y;
        acc.z += w0 * v0.z + w1 * v1.z + w2 * v2.z + w3 * v3.z;
        acc.w += w0 * v0.w + w1 * v1.w + w2 * v2.w + w3 * v3.w;
    }
    for (; e < end; e++) {
        const int2 p = __ldg(&g_csr[e]);
        const float w = __int_as_float(p.y);
        const float4 v = __ldg(((const float4*)(x + (size_t)p.x * IN_DIM)) + lane);
        acc.x += w * v.x; acc.y += w * v.y; acc.z += w * v.z; acc.w += w * v.w;
    }
    // pre-round to tf32 so the fused gemm needs no per-fragment fixup
    acc.x = wmma::__float_to_tf32(acc.x);
    acc.y = wmma::__float_to_tf32(acc.y);
    acc.z = wmma::__float_to_tf32(acc.z);
    acc.w = wmma::__float_to_tf32(acc.w);
    ((float4*)(aggx + (size_t)n * IN_DIM))[lane] = acc;
}

// -------- gather SpMM layer 2: out[n] = b2 + sum w_e * t2[src]  (halfwarp/node) --------
__global__ __launch_bounds__(256) void gather2(const float* __restrict__ t2,
                                               const float* __restrict__ b2,
                                               float* __restrict__ out) {
    const int n = (blockIdx.x * 256 + threadIdx.x) >> 4;
    const int lane = threadIdx.x & 15;
    if (n >= N_NODES) return;
    const int beg = g_ptrl[n] + g_blkx[n >> 8];
    const int end = g_ptrl[n + 1] + g_blkx[(n + 1) >> 8];
    float4 acc = __ldg(((const float4*)b2) + lane);
    int e = beg;
    for (; e + 4 <= end; e += 4) {
        const int2 p0 = __ldg(&g_csr[e + 0]);
        const int2 p1 = __ldg(&g_csr[e + 1]);
        const int2 p2 = __ldg(&g_csr[e + 2]);
        const int2 p3 = __ldg(&g_csr[e + 3]);
        const float4 v0 = __ldg(((const float4*)(t2 + (size_t)p0.x * OUT_DIM)) + lane);
        const float4 v1 = __ldg(((const float4*)(t2 + (size_t)p1.x * OUT_DIM)) + lane);
        const float4 v2 = __ldg(((const float4*)(t2 + (size_t)p2.x * OUT_DIM)) + lane);
        const float4 v3 = __ldg(((const float4*)(t2 + (size_t)p3.x * OUT_DIM)) + lane);
        const float w0 = __int_as_float(p0.y), w1 = __int_as_float(p1.y);
        const float w2 = __int_as_float(p2.y), w3 = __int_as_float(p3.y);
        acc.x += w0 * v0.x + w1 * v1.x + w2 * v2.x + w3 * v3.x;
        acc.y += w0 * v0.y + w1 * v1.y + w2 * v2.y + w3 * v3.y;
        acc.z += w0 * v0.z + w1 * v1.z + w2 * v2.z + w3 * v3.z;
        acc.w += w0 * v0.w + w1 * v1.w + w2 * v2.w + w3 * v3.w;
    }
    for (; e < end; e++) {
        const int2 p = __ldg(&g_csr[e]);
        const float w = __int_as_float(p.y);
        const float4 v = __ldg(((const float4*)(t2 + (size_t)p.x * OUT_DIM)) + lane);
        acc.x += w * v.x; acc.y += w * v.y; acc.z += w * v.z; acc.w += w * v.w;
    }
    ((float4*)(out + (size_t)n * OUT_DIM))[lane] = acc;
}

// -------- fused GEMM: t2 = relu(aggx @ W1 + b1) @ W2  (tf32 tensor cores) --------
// 256 thr / 8 warps / 128 rows. smem = 102.5 KB -> 2 blocks/SM (regs capped 128).
#define LDW1 132
#define LDW2 72

__global__ __launch_bounds__(256, 2) void fused_gemm(const float* __restrict__ A,
                                                     const float* __restrict__ W1g,
                                                     const float* __restrict__ b1g,
                                                     const float* __restrict__ W2g,
                                                     float* __restrict__ t2) {
    extern __shared__ float smem[];
    float* sW1 = smem;                          // 128 x LDW1 (later: staging)
    float* sW2 = sW1 + 128 * LDW1;              // 128 x LDW2
    float* sB1 = sW2 + 128 * LDW2;              // 128

    const int t = threadIdx.x;
    for (int i = t; i < 128 * 128; i += 256)
        sW1[(i >> 7) * LDW1 + (i & 127)] = wmma::__float_to_tf32(W1g[i]);
    for (int i = t; i < 128 * 64; i += 256)
        sW2[(i >> 6) * LDW2 + (i & 63)] = wmma::__float_to_tf32(W2g[i]);
    if (t < 128) sB1[t] = b1g[t];
    __syncthreads();

    const int warp = t >> 5;
    const int lane = t & 31;
    const size_t row0 = (size_t)blockIdx.x * 128 + warp * 16;
    float* stg = sW1 + warp * 16 * LDW1;        // this warp's staging strip

    wmma::fragment<wmma::matrix_a, 16, 16, 8, wmma::precision::tf32, wmma::row_major> af;
    wmma::fragment<wmma::matrix_b, 16, 16, 8, wmma::precision::tf32, wmma::row_major> bf;

    // ---- stage 1: acc = A_strip @ W1 ----
    {
        wmma::fragment<wmma::accumulator, 16, 16, 8, float> acc[8];
        #pragma unroll
        for (int n = 0; n < 8; n++) wmma::fill_fragment(acc[n], 0.f);

        #pragma unroll
        for (int k = 0; k < 16; k++) {
            wmma::load_matrix_sync(af, A + row0 * 128 + k * 8, 128);  // already tf32
            #pragma unroll
            for (int n = 0; n < 8; n++) {
                wmma::load_matrix_sync(bf, sW1 + (k * 8) * LDW1 + n * 16, LDW1);
                wmma::mma_sync(acc[n], af, bf, acc[n]);
            }
        }
        __syncthreads();   // all warps done reading W1 -> safe to overwrite
        #pragma unroll
        for (int n = 0; n < 8; n++)
            wmma::store_matrix_sync(stg + n * 16, acc[n], LDW1, wmma::mem_row_major);
    }
    __syncwarp();

    // ---- bias + relu + tf32-round on this warp's strip (in smem) ----
    for (int i = lane; i < 16 * 32; i += 32) {   // 16 rows x 32 float4
        const int r = i >> 5;
        const int c4 = (i & 31) * 4;
        float* p = stg + r * LDW1 + c4;
        p[0] = wmma::__float_to_tf32(fmaxf(p[0] + sB1[c4 + 0], 0.f));
        p[1] = wmma::__float_to_tf32(fmaxf(p[1] + sB1[c4 + 1], 0.f));
        p[2] = wmma::__float_to_tf32(fmaxf(p[2] + sB1[c4 + 2], 0.f));
        p[3] = wmma::__float_to_tf32(fmaxf(p[3] + sB1[c4 + 3], 0.f));
    }
    __syncwarp();

    // ---- stage 2: t2_strip = strip @ W2 ----
    {
        wmma::fragment<wmma::accumulator, 16, 16, 8, float> acc2[4];
        #pragma unroll
        for (int n = 0; n < 4; n++) wmma::fill_fragment(acc2[n], 0.f);

        #pragma unroll
        for (int k = 0; k < 16; k++) {
            wmma::load_matrix_sync(af, stg + k * 8, LDW1);
            #pragma unroll
            for (int n = 0; n < 4; n++) {
                wmma::load_matrix_sync(bf, sW2 + (k * 8) * LDW2 + n * 16, LDW2);
                wmma::mma_sync(acc2[n], af, bf, acc2[n]);
            }
        }
        #pragma unroll
        for (int n = 0; n < 4; n++)
            wmma::store_matrix_sync(t2 + row0 * 64 + n * 16, acc2[n],
                                    64, wmma::mem_row_major);
    }
}

extern "C" void kernel_launch(void* const* d_in, const int* in_sizes, int n_in,
                              void* d_out, int out_size) {
    // Identify inputs by element count (robust to metadata ordering)
    const float* x  = nullptr; const void* ei = nullptr; const float* ew = nullptr;
    const float* W1 = nullptr; const float* b1 = nullptr;
    const float* W2 = nullptr; const float* b2 = nullptr;
    for (int i = 0; i < n_in; i++) {
        switch (in_sizes[i]) {
            case 12800000: x  = (const float*)d_in[i]; break;
            case 1200000:  ei = d_in[i];               break;
            case 600000:   ew = (const float*)d_in[i]; break;
            case 16384:    W1 = (const float*)d_in[i]; break;
            case 128:      b1 = (const float*)d_in[i]; break;
            case 8192:     W2 = (const float*)d_in[i]; break;
            case 64:       b2 = (const float*)d_in[i]; break;
            default: break;
        }
    }
    float* out = (float*)d_out;
    const int E = N_EDGES;

    float* aggx; cudaGetSymbolAddress((void**)&aggx, g_aggx_v);
    float* t2;   cudaGetSymbolAddress((void**)&t2,   g_t2_v);

    const int smemF = (128 * LDW1 + 128 * LDW2 + 128) * 4;   // 102.5 KB
    cudaFuncSetAttribute(fused_gemm, cudaFuncAttributeMaxDynamicSharedMemorySize,
                         smemF);

    // --- CSR build: decode + scan1 + scan2 + fill (g_cnt re-zeroed in fill) ---
    decode_edges<<<(E + 255) / 256, 256>>>(ei, E);
    scan1<<<SCAN_BLOCKS, 256>>>();
    scan2<<<1, 512>>>();
    fill_csr<<<(E + 255) / 256, 256>>>(ew, E);

    // --- layer 1: aggx = tf32(A @ x)  (pull-mode gather, warp per node) ---
    gather1<<<(N_NODES * 32 + 255) / 256, 256>>>(x, aggx);

    // --- t2 = relu(aggx @ W1 + b1) @ W2  (single fused launch) ---
    const int gblocks = (N_NODES + 127) / 128;  // 782 (padding covers tail rows)
    fused_gemm<<<gblocks, 256, smemF>>>(aggx, W1, b1, W2, t2);

    // --- layer 2: out = b2 + A @ t2  (half-warp per node) ---
    gather2<<<(N_NODES * 16 + 255) / 256, 256>>>(t2, b2, out);
}

// round 17
// speedup vs baseline: 1.4776x; 1.0162x over previous
#include <cuda_runtime.h>
#include <cuda_bf16.h>
#include <mma.h>
#include <cstdint>

using namespace nvcuda;

// Problem constants (match reference setup_inputs)
#define N_NODES 100000
#define N_EDGES 600000
#define IN_DIM  128
#define OUT_DIM 64
#define PAD_ROWS 128
#define SCAN_BLOCKS ((N_NODES + 255) / 256)   // 391

// -------- device-global scratch (no allocations allowed) --------
__device__ float4 g_aggx_v[(size_t)(N_NODES + PAD_ROWS) * IN_DIM / 4];  // A @ x (tf32)
__device__ float4 g_t2_v[(size_t)(N_NODES + PAD_ROWS) * OUT_DIM / 4];   // fused gemm out
__device__ int    g_src[N_EDGES];
__device__ int    g_dst[N_EDGES];
__device__ int    g_ord[N_EDGES];      // per-dst ordinal from decode's atomic
__device__ int    g_cnt[N_NODES];      // zero-init; re-zeroed by fill_csr each call
__device__ int    g_ptrl[N_NODES + 1]; // block-LOCAL exclusive prefix of degrees
__device__ int    g_blkx[SCAN_BLOCKS]; // exclusive prefix of block sums
__device__ int    g_blk[SCAN_BLOCKS];  // block sums
__device__ int2   g_csr[N_EDGES];      // packed {src, float_bits(w)}
// final ptr of node m = g_ptrl[m] + g_blkx[m >> 8]

// -------- edge-index decode (int32/int64 autodetect) + degree/ordinal --------
__device__ __forceinline__ bool ei_is_int64(const void* p) {
    const long long* q = (const long long*)p;
    #pragma unroll
    for (int i = 0; i < 4; i++) {
        long long v = q[i];
        if (v < 0 || v >= N_NODES) return false;
    }
    return true;
}

__global__ __launch_bounds__(256) void decode_edges(const void* __restrict__ ei, int E) {
    int e = blockIdx.x * blockDim.x + threadIdx.x;
    if (e >= E) return;
    long long s, d;
    if (ei_is_int64(ei)) {
        const long long* q = (const long long*)ei;
        s = q[e]; d = q[(size_t)E + e];
    } else {
        const int* q = (const int*)ei;
        s = q[e]; d = q[(size_t)E + e];
    }
    if (s < 0 || s >= N_NODES) s = 0;
    if (d < 0 || d >= N_NODES) d = 0;
    g_src[e] = (int)s;
    g_dst[e] = (int)d;
    g_ord[e] = atomicAdd(&g_cnt[(int)d], 1);   // degree count + unique ordinal
}

// -------- scan1: per-256-block shfl scan of degrees --------
__global__ __launch_bounds__(256) void scan1() {
    __shared__ int wsum[8];
    const int tid = threadIdx.x;
    const int i = blockIdx.x * 256 + tid;
    const int lane = tid & 31;
    const int w = tid >> 5;

    int v = (i < N_NODES) ? g_cnt[i] : 0;
    int x = v;
    #pragma unroll
    for (int o = 1; o < 32; o <<= 1) {
        int t = __shfl_up_sync(0xFFFFFFFFu, x, o);
        if (lane >= o) x += t;
    }
    if (lane == 31) wsum[w] = x;
    __syncthreads();
    if (w == 0) {
        int y = (lane < 8) ? wsum[lane] : 0;
        #pragma unroll
        for (int o = 1; o < 8; o <<= 1) {
            int t = __shfl_up_sync(0xFFFFFFFFu, y, o);
            if (lane >= o) y += t;
        }
        if (lane < 8) wsum[lane] = y;
    }
    __syncthreads();
    const int incl = x + (w > 0 ? wsum[w - 1] : 0);
    if (i < N_NODES) g_ptrl[i] = incl - v;          // block-local exclusive
    if (i == N_NODES - 1) g_ptrl[N_NODES] = incl;   // boundary (same block: 390)
    if (tid == 255) g_blk[blockIdx.x] = wsum[7];    // block total
}

// -------- scan2: one block, exclusive shfl scan of the 391 block sums --------
__global__ __launch_bounds__(512) void scan2() {
    __shared__ int wsum[16];
    const int tid = threadIdx.x;
    const int lane = tid & 31;
    const int w = tid >> 5;
    int v = (tid < SCAN_BLOCKS) ? g_blk[tid] : 0;
    int x = v;
    #pragma unroll
    for (int o = 1; o < 32; o <<= 1) {
        int t = __shfl_up_sync(0xFFFFFFFFu, x, o);
        if (lane >= o) x += t;
    }
    if (lane == 31) wsum[w] = x;
    __syncthreads();
    if (w == 0) {
        int y = (lane < 16) ? wsum[lane] : 0;
        #pragma unroll
        for (int o = 1; o < 16; o <<= 1) {
            int t = __shfl_up_sync(0xFFFFFFFFu, y, o);
            if (lane >= o) y += t;
        }
        if (lane < 16) wsum[lane] = y;
    }
    __syncthreads();
    const int excl = x - v + (w > 0 ? wsum[w - 1] : 0);
    if (tid < SCAN_BLOCKS) g_blkx[tid] = excl;
}

// -------- fill CSR: no atomics; also re-zeroes g_cnt for the next replay --------
__global__ __launch_bounds__(256) void fill_csr(const float* __restrict__ ew, int E) {
    int e = blockIdx.x * blockDim.x + threadIdx.x;
    if (e < N_NODES) g_cnt[e] = 0;
    if (e >= E) return;
    const int d = g_dst[e];
    const int pos = g_ptrl[d] + g_blkx[d >> 8] + g_ord[e];
    g_csr[pos] = make_int2(g_src[e], __float_as_int(ew[e]));
}

// -------- gather SpMM layer 1: aggx[n] = tf32(sum w_e * x[src_e])  (warp/node) --------
__global__ __launch_bounds__(256) void gather1(const float* __restrict__ x,
                                               float* __restrict__ aggx) {
    const int n = (blockIdx.x * 256 + threadIdx.x) >> 5;
    const int lane = threadIdx.x & 31;
    if (n >= N_NODES) return;
    const int beg = g_ptrl[n] + g_blkx[n >> 8];
    const int end = g_ptrl[n + 1] + g_blkx[(n + 1) >> 8];
    float4 acc = make_float4(0.f, 0.f, 0.f, 0.f);
    int e = beg;
    for (; e + 4 <= end; e += 4) {
        const int2 p0 = __ldg(&g_csr[e + 0]);
        const int2 p1 = __ldg(&g_csr[e + 1]);
        const int2 p2 = __ldg(&g_csr[e + 2]);
        const int2 p3 = __ldg(&g_csr[e + 3]);
        const float4 v0 = __ldg(((const float4*)(x + (size_t)p0.x * IN_DIM)) + lane);
        const float4 v1 = __ldg(((const float4*)(x + (size_t)p1.x * IN_DIM)) + lane);
        const float4 v2 = __ldg(((const float4*)(x + (size_t)p2.x * IN_DIM)) + lane);
        const float4 v3 = __ldg(((const float4*)(x + (size_t)p3.x * IN_DIM)) + lane);
        const float w0 = __int_as_float(p0.y), w1 = __int_as_float(p1.y);
        const float w2 = __int_as_float(p2.y), w3 = __int_as_float(p3.y);
        acc.x += w0 * v0.x + w1 * v1.x + w2 * v2.x + w3 * v3.x;
        acc.y += w0 * v0.y + w1 * v1.y + w2 * v2.y + w3 * v3.y;
        acc.z += w0 * v0.z + w1 * v1.z + w2 * v2.z + w3 * v3.z;
        acc.w += w0 * v0.w + w1 * v1.w + w2 * v2.w + w3 * v3.w;
    }
    for (; e < end; e++) {
        const int2 p = __ldg(&g_csr[e]);
        const float w = __int_as_float(p.y);
        const float4 v = __ldg(((const float4*)(x + (size_t)p.x * IN_DIM)) + lane);
        acc.x += w * v.x; acc.y += w * v.y; acc.z += w * v.z; acc.w += w * v.w;
    }
    // pre-round to tf32 so the fused gemm needs no per-fragment fixup
    acc.x = wmma::__float_to_tf32(acc.x);
    acc.y = wmma::__float_to_tf32(acc.y);
    acc.z = wmma::__float_to_tf32(acc.z);
    acc.w = wmma::__float_to_tf32(acc.w);
    ((float4*)(aggx + (size_t)n * IN_DIM))[lane] = acc;
}

// -------- gather SpMM layer 2: out[n] = b2 + sum w_e * t2[src]  (halfwarp/node) --------
__global__ __launch_bounds__(256) void gather2(const float* __restrict__ t2,
                                               const float* __restrict__ b2,
                                               float* __restrict__ out) {
    const int n = (blockIdx.x * 256 + threadIdx.x) >> 4;
    const int lane = threadIdx.x & 15;
    if (n >= N_NODES) return;
    const int beg = g_ptrl[n] + g_blkx[n >> 8];
    const int end = g_ptrl[n + 1] + g_blkx[(n + 1) >> 8];
    float4 acc = __ldg(((const float4*)b2) + lane);
    int e = beg;
    for (; e + 4 <= end; e += 4) {
        const int2 p0 = __ldg(&g_csr[e + 0]);
        const int2 p1 = __ldg(&g_csr[e + 1]);
        const int2 p2 = __ldg(&g_csr[e + 2]);
        const int2 p3 = __ldg(&g_csr[e + 3]);
        const float4 v0 = __ldg(((const float4*)(t2 + (size_t)p0.x * OUT_DIM)) + lane);
        const float4 v1 = __ldg(((const float4*)(t2 + (size_t)p1.x * OUT_DIM)) + lane);
        const float4 v2 = __ldg(((const float4*)(t2 + (size_t)p2.x * OUT_DIM)) + lane);
        const float4 v3 = __ldg(((const float4*)(t2 + (size_t)p3.x * OUT_DIM)) + lane);
        const float w0 = __int_as_float(p0.y), w1 = __int_as_float(p1.y);
        const float w2 = __int_as_float(p2.y), w3 = __int_as_float(p3.y);
        acc.x += w0 * v0.x + w1 * v1.x + w2 * v2.x + w3 * v3.x;
        acc.y += w0 * v0.y + w1 * v1.y + w2 * v2.y + w3 * v3.y;
        acc.z += w0 * v0.z + w1 * v1.z + w2 * v2.z + w3 * v3.z;
        acc.w += w0 * v0.w + w1 * v1.w + w2 * v2.w + w3 * v3.w;
    }
    for (; e < end; e++) {
        const int2 p = __ldg(&g_csr[e]);
        const float w = __int_as_float(p.y);
        const float4 v = __ldg(((const float4*)(t2 + (size_t)p.x * OUT_DIM)) + lane);
        acc.x += w * v.x; acc.y += w * v.y; acc.z += w * v.z; acc.w += w * v.w;
    }
    ((float4*)(out + (size_t)n * OUT_DIM))[lane] = acc;
}

// -------- fused GEMM: t2 = relu(aggx @ W1 + b1) @ W2  (tf32 tensor cores) --------
// 256 thr / 8 warps / 128 rows. smem = 110.5 KB -> 2 blocks/SM (regs capped 128).
// A k-slices are double-buffered in smem via cp.async (register-neutral
// prefetch): the MMA chain consumes slice k from smem (~29 cyc) while the
// DMA engine pulls slice k+1 from L2 — the ~250-cycle global fragment load
// leaves the critical path.
#define LDW1 132
#define LDW2 72
#define LDA  8      // A-slice leading dim (floats); 8 floats = 32B rows

__global__ __launch_bounds__(256, 2) void fused_gemm(const float* __restrict__ A,
                                                     const float* __restrict__ W1g,
                                                     const float* __restrict__ b1g,
                                                     const float* __restrict__ W2g,
                                                     float* __restrict__ t2) {
    extern __shared__ float smem[];
    float* sW1 = smem;                          // 128 x LDW1 (later: staging)
    float* sW2 = sW1 + 128 * LDW1;              // 128 x LDW2
    float* sB1 = sW2 + 128 * LDW2;              // 128
    float* sA  = sB1 + 128;                     // 2 x 128 x LDA (A slice dbl-buf)

    const int t = threadIdx.x;
    for (int i = t; i < 128 * 128; i += 256)
        sW1[(i >> 7) * LDW1 + (i & 127)] = wmma::__float_to_tf32(W1g[i]);
    for (int i = t; i < 128 * 64; i += 256)
        sW2[(i >> 6) * LDW2 + (i & 63)] = wmma::__float_to_tf32(W2g[i]);
    if (t < 128) sB1[t] = b1g[t];

    const int warp = t >> 5;
    const int lane = t & 31;
    const size_t row0 = (size_t)blockIdx.x * 128 + warp * 16;
    float* stg = sW1 + warp * 16 * LDW1;        // this warp's staging strip
    const float* Ablk = A + (size_t)blockIdx.x * 128 * 128;

    // cp.async prefetch of A slice k into buffer b: 128 rows x 8 cols.
    // Each thread copies one 16B half-row: row = t>>1, half = t&1.
    const int pf_row  = t >> 1;
    const int pf_half = t & 1;
    {
        // prefetch k = 0 into buffer 0 (overlaps the weight staging above)
        const float* gsrc = Ablk + pf_row * 128 + 0 * 8 + pf_half * 4;
        uint32_t sdst = (uint32_t)__cvta_generic_to_shared(
            sA + 0 * 128 * LDA + pf_row * LDA + pf_half * 4);
        asm volatile("cp.async.cg.shared.global [%0], [%1], 16;\n"
                     :: "r"(sdst), "l"(gsrc));
        asm volatile("cp.async.commit_group;\n");
    }
    __syncthreads();   // weights staged (also covers first-slice ordering below)

    wmma::fragment<wmma::matrix_a, 16, 16, 8, wmma::precision::tf32, wmma::row_major> af;
    wmma::fragment<wmma::matrix_b, 16, 16, 8, wmma::precision::tf32, wmma::row_major> bf;

    // ---- stage 1: acc = A_strip @ W1, A via smem double buffer ----
    {
        wmma::fragment<wmma::accumulator, 16, 16, 8, float> acc[8];
        #pragma unroll
        for (int n = 0; n < 8; n++) wmma::fill_fragment(acc[n], 0.f);

        #pragma unroll
        for (int k = 0; k < 16; k++) {
            asm volatile("cp.async.wait_group 0;\n");
            __syncthreads();                     // buf[k&1] ready, prior reads done
            if (k < 15) {                        // prefetch k+1 into other buffer
                const float* gsrc = Ablk + pf_row * 128 + (k + 1) * 8 + pf_half * 4;
                uint32_t sdst = (uint32_t)__cvta_generic_to_shared(
                    sA + ((k + 1) & 1) * 128 * LDA + pf_row * LDA + pf_half * 4);
                asm volatile("cp.async.cg.shared.global [%0], [%1], 16;\n"
                             :: "r"(sdst), "l"(gsrc));
                asm volatile("cp.async.commit_group;\n");
            }
            wmma::load_matrix_sync(af, sA + (k & 1) * 128 * LDA + warp * 16 * LDA, LDA);
            #pragma unroll
            for (int n = 0; n < 8; n++) {
                wmma::load_matrix_sync(bf, sW1 + (k * 8) * LDW1 + n * 16, LDW1);
                wmma::mma_sync(acc[n], af, bf, acc[n]);
            }
        }
        __syncthreads();   // all warps done reading W1 -> safe to overwrite
        #pragma unroll
        for (int n = 0; n < 8; n++)
            wmma::store_matrix_sync(stg + n * 16, acc[n], LDW1, wmma::mem_row_major);
    }
    __syncwarp();

    // ---- bias + relu + tf32-round on this warp's strip (in smem) ----
    for (int i = lane; i < 16 * 32; i += 32) {   // 16 rows x 32 float4
        const int r = i >> 5;
        const int c4 = (i & 31) * 4;
        float* p = stg + r * LDW1 + c4;
        p[0] = wmma::__float_to_tf32(fmaxf(p[0] + sB1[c4 + 0], 0.f));
        p[1] = wmma::__float_to_tf32(fmaxf(p[1] + sB1[c4 + 1], 0.f));
        p[2] = wmma::__float_to_tf32(fmaxf(p[2] + sB1[c4 + 2], 0.f));
        p[3] = wmma::__float_to_tf32(fmaxf(p[3] + sB1[c4 + 3], 0.f));
    }
    __syncwarp();

    // ---- stage 2: t2_strip = strip @ W2 ----
    {
        wmma::fragment<wmma::accumulator, 16, 16, 8, float> acc2[4];
        #pragma unroll
        for (int n = 0; n < 4; n++) wmma::fill_fragment(acc2[n], 0.f);

        #pragma unroll
        for (int k = 0; k < 16; k++) {
            wmma::load_matrix_sync(af, stg + k * 8, LDW1);
            #pragma unroll
            for (int n = 0; n < 4; n++) {
                wmma::load_matrix_sync(bf, sW2 + (k * 8) * LDW2 + n * 16, LDW2);
                wmma::mma_sync(acc2[n], af, bf, acc2[n]);
            }
        }
        #pragma unroll
        for (int n = 0; n < 4; n++)
            wmma::store_matrix_sync(t2 + row0 * 64 + n * 16, acc2[n],
                                    64, wmma::mem_row_major);
    }
}

extern "C" void kernel_launch(void* const* d_in, const int* in_sizes, int n_in,
                              void* d_out, int out_size) {
    // Identify inputs by element count (robust to metadata ordering)
    const float* x  = nullptr; const void* ei = nullptr; const float* ew = nullptr;
    const float* W1 = nullptr; const float* b1 = nullptr;
    const float* W2 = nullptr; const float* b2 = nullptr;
    for (int i = 0; i < n_in; i++) {
        switch (in_sizes[i]) {
            case 12800000: x  = (const float*)d_in[i]; break;
            case 1200000:  ei = d_in[i];               break;
            case 600000:   ew = (const float*)d_in[i]; break;
            case 16384:    W1 = (const float*)d_in[i]; break;
            case 128:      b1 = (const float*)d_in[i]; break;
            case 8192:     W2 = (const float*)d_in[i]; break;
            case 64:       b2 = (const float*)d_in[i]; break;
            default: break;
        }
    }
    float* out = (float*)d_out;
    const int E = N_EDGES;

    float* aggx; cudaGetSymbolAddress((void**)&aggx, g_aggx_v);
    float* t2;   cudaGetSymbolAddress((void**)&t2,   g_t2_v);

    const int smemF = (128 * LDW1 + 128 * LDW2 + 128 + 2 * 128 * LDA) * 4; // 110.5 KB
    cudaFuncSetAttribute(fused_gemm, cudaFuncAttributeMaxDynamicSharedMemorySize,
                         smemF);

    // --- CSR build: decode + scan1 + scan2 + fill (g_cnt re-zeroed in fill) ---
    decode_edges<<<(E + 255) / 256, 256>>>(ei, E);
    scan1<<<SCAN_BLOCKS, 256>>>();
    scan2<<<1, 512>>>();
    fill_csr<<<(E + 255) / 256, 256>>>(ew, E);

    // --- layer 1: aggx = tf32(A @ x)  (pull-mode gather, warp per node) ---
    gather1<<<(N_NODES * 32 + 255) / 256, 256>>>(x, aggx);

    // --- t2 = relu(aggx @ W1 + b1) @ W2  (single fused launch) ---
    const int gblocks = (N_NODES + 127) / 128;  // 782 (padding covers tail rows)
    fused_gemm<<<gblocks, 256, smemF>>>(aggx, W1, b1, W2, t2);

    // --- layer 2: out = b2 + A @ t2  (half-warp per node) ---
    gather2<<<(N_NODES * 16 + 255) / 256, 256>>>(t2, b2, out);
}